// round 3
// baseline (speedup 1.0000x reference)
#include <cuda_runtime.h>
#include <math.h>

#define N_ENT_MAX 150016
#define H 128
#define DEG 32
#define TOPK 10

// -------- device scratch (no allocs allowed) --------
__device__ float g_h_node[N_ENT_MAX * H];
__device__ float g_s_src[N_ENT_MAX];
__device__ float g_s_dst[N_ENT_MAX];
__device__ float g_h_rel[512 * H];
__device__ float g_s_rel[512];

// -------- packed f32x2 helpers (ptxas never auto-fuses; PTX-only path) -----
__device__ __forceinline__ unsigned long long pack2(float v) {
    unsigned long long r; unsigned int u = __float_as_uint(v);
    asm("mov.b64 %0, {%1, %1};" : "=l"(r) : "r"(u));
    return r;
}
__device__ __forceinline__ void ffma2(unsigned long long& acc,
                                      unsigned long long a, unsigned long long b) {
    asm("fma.rn.f32x2 %0, %1, %2, %0;" : "+l"(acc) : "l"(a), "l"(b));
}
__device__ __forceinline__ float2 unpack2(unsigned long long v) {
    unsigned int a, b;
    asm("mov.b64 {%0, %1}, %2;" : "=r"(a), "=r"(b) : "l"(v));
    return make_float2(__uint_as_float(a), __uint_as_float(b));
}

// ===================== kernel A: h_rel + s_rel (tiny) ======================
__global__ void krel(const float* __restrict__ rel_emb,
                     const float* __restrict__ W_r,
                     const float* __restrict__ a) {
    int r = blockIdx.x;
    int j = threadIdx.x;                 // 128 threads
    const float* x = rel_emb + r * H;
    float acc = 0.f;
#pragma unroll 8
    for (int h = 0; h < H; ++h) acc = fmaf(x[h], W_r[h * H + j], acc);
    g_h_rel[r * H + j] = acc;
    __shared__ float red[H];
    red[j] = acc * a[2 * H + j];
    __syncthreads();
    for (int off = 64; off > 0; off >>= 1) {
        if (j < off) red[j] += red[j + off];
        __syncthreads();
    }
    if (j == 0) g_s_rel[r] = red[0];
}

// ============ kernel B: h_node = ent_emb @ W, s_src, s_dst ================
// 256 threads = 8 warps, 4 rows per warp, W + a1/a2 + x-rows staged in smem.
#define B_WARPS 8
#define B_RPW 4
__global__ void __launch_bounds__(256) knode(const float* __restrict__ ent,
                                             const float* __restrict__ W,
                                             const float* __restrict__ a, int n) {
    extern __shared__ float sm[];
    float* Ws  = sm;                  // 16384
    float* a1s = Ws + H * H;          // 128
    float* a2s = a1s + H;             // 128
    float* xs  = a2s + H;             // 8*4*128
    int tid = threadIdx.x;
    for (int i = tid; i < H * H; i += blockDim.x) Ws[i] = W[i];
    if (tid < H) { a1s[tid] = a[tid]; a2s[tid] = a[H + tid]; }
    __syncthreads();

    int w = tid >> 5, l = tid & 31;
    int row0 = blockIdx.x * (B_WARPS * B_RPW) + w * B_RPW;
    float* xw = xs + w * (B_RPW * H);

#pragma unroll
    for (int r = 0; r < B_RPW; r++) {
        int row = row0 + r;
        float4 v = make_float4(0.f, 0.f, 0.f, 0.f);
        if (row < n) v = *(const float4*)(ent + row * H + 4 * l);
        *(float4*)(xw + r * H + 4 * l) = v;
    }
    __syncwarp();

    unsigned long long acc[B_RPW][2];
#pragma unroll
    for (int r = 0; r < B_RPW; r++) { acc[r][0] = 0ull; acc[r][1] = 0ull; }

    for (int h4 = 0; h4 < H / 4; ++h4) {
        float4 x0 = *(const float4*)(xw + 0 * H + h4 * 4);   // broadcast LDS
        float4 x1 = *(const float4*)(xw + 1 * H + h4 * 4);
        float4 x2 = *(const float4*)(xw + 2 * H + h4 * 4);
        float4 x3 = *(const float4*)(xw + 3 * H + h4 * 4);
#pragma unroll
        for (int q = 0; q < 4; q++) {
            ulonglong2 wv = *(const ulonglong2*)(Ws + (h4 * 4 + q) * H + 4 * l);
            unsigned long long b0 = pack2(((const float*)&x0)[q]);
            unsigned long long b1 = pack2(((const float*)&x1)[q]);
            unsigned long long b2 = pack2(((const float*)&x2)[q]);
            unsigned long long b3 = pack2(((const float*)&x3)[q]);
            ffma2(acc[0][0], b0, wv.x); ffma2(acc[0][1], b0, wv.y);
            ffma2(acc[1][0], b1, wv.x); ffma2(acc[1][1], b1, wv.y);
            ffma2(acc[2][0], b2, wv.x); ffma2(acc[2][1], b2, wv.y);
            ffma2(acc[3][0], b3, wv.x); ffma2(acc[3][1], b3, wv.y);
        }
    }

    float4 a1v = *(const float4*)(a1s + 4 * l);
    float4 a2v = *(const float4*)(a2s + 4 * l);
#pragma unroll
    for (int r = 0; r < B_RPW; r++) {
        int row = row0 + r;
        if (row >= n) continue;          // uniform across warp
        float2 lo = unpack2(acc[r][0]), hi = unpack2(acc[r][1]);
        float4 o = make_float4(lo.x, lo.y, hi.x, hi.y);
        *(float4*)(g_h_node + row * H + 4 * l) = o;
        float p1 = o.x * a1v.x + o.y * a1v.y + o.z * a1v.z + o.w * a1v.w;
        float p2 = o.x * a2v.x + o.y * a2v.y + o.z * a2v.z + o.w * a2v.w;
#pragma unroll
        for (int off = 16; off; off >>= 1) {
            p1 += __shfl_xor_sync(0xffffffffu, p1, off);
            p2 += __shfl_xor_sync(0xffffffffu, p2, off);
        }
        if (l == 0) { g_s_src[row] = p1; g_s_dst[row] = p2; }
    }
}

// == kernel C: score -> top10 -> softmax -> gather-agg -> @neigh_w -> tanh ==
#define C_WARPS 8
__global__ void __launch_bounds__(256) kattend(const int* __restrict__ src,
                                               const int* __restrict__ rid,
                                               const float* __restrict__ nw,
                                               float* __restrict__ out, int n) {
    extern __shared__ float sm[];
    float* nws   = sm;                       // 16384
    float* neigh = nws + H * H;              // 8*128
    float* ats   = neigh + C_WARPS * H;      // 8*16
    int*   sks   = (int*)(ats + C_WARPS * 16);   // 8*16
    int*   rks   = sks + C_WARPS * 16;           // 8*16
    int tid = threadIdx.x;
    for (int i = tid; i < H * H; i += blockDim.x) nws[i] = nw[i];
    __syncthreads();

    int w = tid >> 5, l = tid & 31;
    int node = blockIdx.x * C_WARPS + w;
    if (node >= n) return;

    // --- edge scores (DEG == 32 == warp width) ---
    float sdst = g_s_dst[node];
    int s = src[node * DEG + l];
    int r = rid[node * DEG + l];
    float v = (g_s_src[s] + sdst) + g_s_rel[r];
    float sc = (v >= 0.f) ? v : 0.2f * v;

    // --- rank = #{j: v_j > v_i} + #{j<i: v_j == v_i}  (matches lax.top_k) ---
    int rank = 0;
#pragma unroll
    for (int j = 0; j < DEG; j++) {
        float vj = __shfl_sync(0xffffffffu, sc, j);
        rank += (vj > sc) || (vj == sc && j < l);
    }
    bool sel = (rank < TOPK);

    // --- softmax over selected 10 ---
    float m = sel ? sc : __int_as_float(0xff800000);
#pragma unroll
    for (int off = 16; off; off >>= 1) m = fmaxf(m, __shfl_xor_sync(0xffffffffu, m, off));
    float e = sel ? expf(sc - m) : 0.f;
    float z = e;
#pragma unroll
    for (int off = 16; off; off >>= 1) z += __shfl_xor_sync(0xffffffffu, z, off);
    float attn = e / z;

    float* atw = ats + w * 16;
    int*   skw = sks + w * 16;
    int*   rkw = rks + w * 16;
    if (sel) { atw[rank] = attn; skw[rank] = s; rkw[rank] = r; }
    __syncwarp();

    // --- neigh = sum_k attn_k * (h_node[sk] + h_rel[rk]); lane owns 4 dims ---
    float4 acc = make_float4(0.f, 0.f, 0.f, 0.f);
#pragma unroll
    for (int k = 0; k < TOPK; k++) {
        int sk = skw[k], rk = rkw[k];
        float ak = atw[k];
        float4 hn = *(const float4*)(g_h_node + sk * H + 4 * l);
        float4 hr = *(const float4*)(g_h_rel + rk * H + 4 * l);
        acc.x = fmaf(ak, hn.x + hr.x, acc.x);
        acc.y = fmaf(ak, hn.y + hr.y, acc.y);
        acc.z = fmaf(ak, hn.z + hr.z, acc.z);
        acc.w = fmaf(ak, hn.w + hr.w, acc.w);
    }
    float* ng = neigh + w * H;
    *(float4*)(ng + 4 * l) = acc;
    __syncwarp();

    // --- out = tanh(neigh @ neigh_w), packed f32x2 ---
    unsigned long long o0 = 0ull, o1 = 0ull;
    for (int h4 = 0; h4 < H / 4; ++h4) {
        float4 nx = *(const float4*)(ng + h4 * 4);   // broadcast LDS
#pragma unroll
        for (int q = 0; q < 4; q++) {
            ulonglong2 wv = *(const ulonglong2*)(nws + (h4 * 4 + q) * H + 4 * l);
            unsigned long long b = pack2(((const float*)&nx)[q]);
            ffma2(o0, b, wv.x); ffma2(o1, b, wv.y);
        }
    }
    float2 lo = unpack2(o0), hi = unpack2(o1);
    float4 res = make_float4(tanhf(lo.x), tanhf(lo.y), tanhf(hi.x), tanhf(hi.y));
    *(float4*)(out + node * H + 4 * l) = res;
}

// ============================== launch =====================================
extern "C" void kernel_launch(void* const* d_in, const int* in_sizes, int n_in,
                              void* d_out, int out_size) {
    const float* ent = (const float*)d_in[0];
    const float* rel = (const float*)d_in[1];
    const float* W   = (const float*)d_in[2];
    const float* W_r = (const float*)d_in[3];
    const float* a   = (const float*)d_in[4];
    const float* nw  = (const float*)d_in[5];
    const int*   src = (const int*)d_in[6];
    const int*   rid = (const int*)d_in[7];
    float* out = (float*)d_out;

    int n     = in_sizes[0] / H;   // 150000
    int nrel  = in_sizes[1] / H;   // 500

    size_t smB = (size_t)(H * H + 2 * H + B_WARPS * B_RPW * H) * sizeof(float);
    size_t smC = (size_t)(H * H + C_WARPS * H + C_WARPS * 16) * sizeof(float)
               + (size_t)(2 * C_WARPS * 16) * sizeof(int);
    cudaFuncSetAttribute(knode,   cudaFuncAttributeMaxDynamicSharedMemorySize, (int)smB);
    cudaFuncSetAttribute(kattend, cudaFuncAttributeMaxDynamicSharedMemorySize, (int)smC);

    krel<<<nrel, H>>>(rel, W_r, a);
    knode<<<(n + B_WARPS * B_RPW - 1) / (B_WARPS * B_RPW), 256, smB>>>(ent, W, a, n);
    kattend<<<(n + C_WARPS - 1) / C_WARPS, 256, smC>>>(src, rid, nw, out, n);
}

// round 4
// speedup vs baseline: 1.0289x; 1.0289x over previous
#include <cuda_runtime.h>
#include <math.h>

#define N_ENT_MAX 150016
#define H 128
#define DEG 32
#define TOPK 10

// -------- device scratch (no allocs allowed) --------
__device__ float g_h_node[N_ENT_MAX * H];
__device__ float g_neigh[N_ENT_MAX * H];
__device__ float g_s_src[N_ENT_MAX];
__device__ float g_s_dst[N_ENT_MAX];
__device__ float g_h_rel[512 * H];
__device__ float g_s_rel[512];

// -------- packed f32x2 helpers (PTX-only path, 2x FFMA throughput) --------
__device__ __forceinline__ unsigned long long pack2(float v) {
    unsigned long long r; unsigned int u = __float_as_uint(v);
    asm("mov.b64 %0, {%1, %1};" : "=l"(r) : "r"(u));
    return r;
}
__device__ __forceinline__ void ffma2(unsigned long long& acc,
                                      unsigned long long a, unsigned long long b) {
    asm("fma.rn.f32x2 %0, %1, %2, %0;" : "+l"(acc) : "l"(a), "l"(b));
}
__device__ __forceinline__ float2 unpack2(unsigned long long v) {
    unsigned int a, b;
    asm("mov.b64 {%0, %1}, %2;" : "=r"(a), "=r"(b) : "l"(v));
    return make_float2(__uint_as_float(a), __uint_as_float(b));
}

// ===================== kernel A: h_rel + s_rel (tiny) ======================
__global__ void krel(const float* __restrict__ rel_emb,
                     const float* __restrict__ W_r,
                     const float* __restrict__ a) {
    int r = blockIdx.x;
    int j = threadIdx.x;                 // 128 threads
    const float* x = rel_emb + r * H;
    float acc = 0.f;
#pragma unroll 8
    for (int h = 0; h < H; ++h) acc = fmaf(x[h], W_r[h * H + j], acc);
    g_h_rel[r * H + j] = acc;
    __shared__ float red[H];
    red[j] = acc * a[2 * H + j];
    __syncthreads();
    for (int off = 64; off > 0; off >>= 1) {
        if (j < off) red[j] += red[j + off];
        __syncthreads();
    }
    if (j == 0) g_s_rel[r] = red[0];
}

// ============ kernel B: h_node = ent_emb @ W, s_src, s_dst ================
#define B_WARPS 8
#define B_RPW 4
__global__ void __launch_bounds__(256) knode(const float* __restrict__ ent,
                                             const float* __restrict__ W,
                                             const float* __restrict__ a, int n) {
    extern __shared__ float sm[];
    float* Ws  = sm;                  // 16384 floats
    float* a1s = Ws + H * H;
    float* a2s = a1s + H;
    float* xs  = a2s + H;             // 8*4*128
    int tid = threadIdx.x;
    for (int i = tid; i < H * H; i += blockDim.x) Ws[i] = W[i];
    if (tid < H) { a1s[tid] = a[tid]; a2s[tid] = a[H + tid]; }
    __syncthreads();

    int w = tid >> 5, l = tid & 31;
    int row0 = blockIdx.x * (B_WARPS * B_RPW) + w * B_RPW;
    float* xw = xs + w * (B_RPW * H);

#pragma unroll
    for (int r = 0; r < B_RPW; r++) {
        int row = row0 + r;
        float4 v = make_float4(0.f, 0.f, 0.f, 0.f);
        if (row < n) v = *(const float4*)(ent + row * H + 4 * l);
        *(float4*)(xw + r * H + 4 * l) = v;
    }
    __syncwarp();

    unsigned long long acc[B_RPW][2];
#pragma unroll
    for (int r = 0; r < B_RPW; r++) { acc[r][0] = 0ull; acc[r][1] = 0ull; }

    for (int h4 = 0; h4 < H / 4; ++h4) {
        float4 x0 = *(const float4*)(xw + 0 * H + h4 * 4);   // broadcast LDS
        float4 x1 = *(const float4*)(xw + 1 * H + h4 * 4);
        float4 x2 = *(const float4*)(xw + 2 * H + h4 * 4);
        float4 x3 = *(const float4*)(xw + 3 * H + h4 * 4);
#pragma unroll
        for (int q = 0; q < 4; q++) {
            ulonglong2 wv = *(const ulonglong2*)(Ws + (h4 * 4 + q) * H + 4 * l);
            unsigned long long b0 = pack2(((const float*)&x0)[q]);
            unsigned long long b1 = pack2(((const float*)&x1)[q]);
            unsigned long long b2 = pack2(((const float*)&x2)[q]);
            unsigned long long b3 = pack2(((const float*)&x3)[q]);
            ffma2(acc[0][0], b0, wv.x); ffma2(acc[0][1], b0, wv.y);
            ffma2(acc[1][0], b1, wv.x); ffma2(acc[1][1], b1, wv.y);
            ffma2(acc[2][0], b2, wv.x); ffma2(acc[2][1], b2, wv.y);
            ffma2(acc[3][0], b3, wv.x); ffma2(acc[3][1], b3, wv.y);
        }
    }

    float4 a1v = *(const float4*)(a1s + 4 * l);
    float4 a2v = *(const float4*)(a2s + 4 * l);
#pragma unroll
    for (int r = 0; r < B_RPW; r++) {
        int row = row0 + r;
        if (row >= n) continue;          // uniform across warp
        float2 lo = unpack2(acc[r][0]), hi = unpack2(acc[r][1]);
        float4 o = make_float4(lo.x, lo.y, hi.x, hi.y);
        *(float4*)(g_h_node + row * H + 4 * l) = o;
        float p1 = o.x * a1v.x + o.y * a1v.y + o.z * a1v.z + o.w * a1v.w;
        float p2 = o.x * a2v.x + o.y * a2v.y + o.z * a2v.z + o.w * a2v.w;
#pragma unroll
        for (int off = 16; off; off >>= 1) {
            p1 += __shfl_xor_sync(0xffffffffu, p1, off);
            p2 += __shfl_xor_sync(0xffffffffu, p2, off);
        }
        if (l == 0) { g_s_src[row] = p1; g_s_dst[row] = p2; }
    }
}

// ====== kernel C1: score -> top10 -> softmax -> gather-agg -> g_neigh =====
// One warp per node, tiny smem, high occupancy, 20 independent LDG.128/warp.
#define G_WARPS 8
__global__ void __launch_bounds__(256) kgather(const int* __restrict__ src,
                                               const int* __restrict__ rid, int n) {
    __shared__ float ats[G_WARPS][16];
    __shared__ int   sks[G_WARPS][16];
    __shared__ int   rks[G_WARPS][16];
    int tid = threadIdx.x;
    int w = tid >> 5, l = tid & 31;
    int node = blockIdx.x * G_WARPS + w;
    if (node >= n) return;

    // --- edge scores (DEG == 32 == warp width) ---
    float sdst = g_s_dst[node];
    int s = src[node * DEG + l];
    int r = rid[node * DEG + l];
    float v = (g_s_src[s] + sdst) + g_s_rel[r];
    float sc = (v >= 0.f) ? v : 0.2f * v;

    // --- rank = #{j: v_j > v_i} + #{j<i: v_j == v_i}  (matches lax.top_k) ---
    int rank = 0;
#pragma unroll
    for (int j = 0; j < DEG; j++) {
        float vj = __shfl_sync(0xffffffffu, sc, j);
        rank += (vj > sc) || (vj == sc && j < l);
    }
    bool sel = (rank < TOPK);

    // --- softmax over selected 10 ---
    float m = sel ? sc : __int_as_float(0xff800000);
#pragma unroll
    for (int off = 16; off; off >>= 1) m = fmaxf(m, __shfl_xor_sync(0xffffffffu, m, off));
    float e = sel ? expf(sc - m) : 0.f;
    float z = e;
#pragma unroll
    for (int off = 16; off; off >>= 1) z += __shfl_xor_sync(0xffffffffu, z, off);
    float attn = e / z;

    if (sel) { ats[w][rank] = attn; sks[w][rank] = s; rks[w][rank] = r; }
    __syncwarp();

    // --- neigh = sum_k attn_k * (h_node[sk] + h_rel[rk]); lane owns 4 dims --
    float4 acc = make_float4(0.f, 0.f, 0.f, 0.f);
#pragma unroll
    for (int k = 0; k < TOPK; k++) {
        int sk = sks[w][k], rk = rks[w][k];
        float ak = ats[w][k];
        float4 hn = *(const float4*)(g_h_node + sk * H + 4 * l);
        float4 hr = *(const float4*)(g_h_rel + rk * H + 4 * l);
        acc.x = fmaf(ak, hn.x + hr.x, acc.x);
        acc.y = fmaf(ak, hn.y + hr.y, acc.y);
        acc.z = fmaf(ak, hn.z + hr.z, acc.z);
        acc.w = fmaf(ak, hn.w + hr.w, acc.w);
    }
    *(float4*)(g_neigh + node * H + 4 * l) = acc;
}

// ========= kernel C2: out = tanh(g_neigh @ neigh_w), 4 rows/warp ==========
__global__ void __launch_bounds__(256) kout(const float* __restrict__ nw,
                                            float* __restrict__ out, int n) {
    extern __shared__ float sm[];
    float* Ws = sm;                   // 16384 floats
    float* xs = Ws + H * H;           // 8*4*128
    int tid = threadIdx.x;
    for (int i = tid; i < H * H; i += blockDim.x) Ws[i] = nw[i];
    __syncthreads();

    int w = tid >> 5, l = tid & 31;
    int row0 = blockIdx.x * (B_WARPS * B_RPW) + w * B_RPW;
    float* xw = xs + w * (B_RPW * H);

#pragma unroll
    for (int r = 0; r < B_RPW; r++) {
        int row = row0 + r;
        float4 v = make_float4(0.f, 0.f, 0.f, 0.f);
        if (row < n) v = *(const float4*)(g_neigh + row * H + 4 * l);
        *(float4*)(xw + r * H + 4 * l) = v;
    }
    __syncwarp();

    unsigned long long acc[B_RPW][2];
#pragma unroll
    for (int r = 0; r < B_RPW; r++) { acc[r][0] = 0ull; acc[r][1] = 0ull; }

    for (int h4 = 0; h4 < H / 4; ++h4) {
        float4 x0 = *(const float4*)(xw + 0 * H + h4 * 4);
        float4 x1 = *(const float4*)(xw + 1 * H + h4 * 4);
        float4 x2 = *(const float4*)(xw + 2 * H + h4 * 4);
        float4 x3 = *(const float4*)(xw + 3 * H + h4 * 4);
#pragma unroll
        for (int q = 0; q < 4; q++) {
            ulonglong2 wv = *(const ulonglong2*)(Ws + (h4 * 4 + q) * H + 4 * l);
            unsigned long long b0 = pack2(((const float*)&x0)[q]);
            unsigned long long b1 = pack2(((const float*)&x1)[q]);
            unsigned long long b2 = pack2(((const float*)&x2)[q]);
            unsigned long long b3 = pack2(((const float*)&x3)[q]);
            ffma2(acc[0][0], b0, wv.x); ffma2(acc[0][1], b0, wv.y);
            ffma2(acc[1][0], b1, wv.x); ffma2(acc[1][1], b1, wv.y);
            ffma2(acc[2][0], b2, wv.x); ffma2(acc[2][1], b2, wv.y);
            ffma2(acc[3][0], b3, wv.x); ffma2(acc[3][1], b3, wv.y);
        }
    }

#pragma unroll
    for (int r = 0; r < B_RPW; r++) {
        int row = row0 + r;
        if (row >= n) continue;
        float2 lo = unpack2(acc[r][0]), hi = unpack2(acc[r][1]);
        float4 res = make_float4(tanhf(lo.x), tanhf(lo.y), tanhf(hi.x), tanhf(hi.y));
        *(float4*)(out + row * H + 4 * l) = res;
    }
}

// ============================== launch =====================================
extern "C" void kernel_launch(void* const* d_in, const int* in_sizes, int n_in,
                              void* d_out, int out_size) {
    const float* ent = (const float*)d_in[0];
    const float* rel = (const float*)d_in[1];
    const float* W   = (const float*)d_in[2];
    const float* a   = (const float*)d_in[4];
    const float* W_r = (const float*)d_in[3];
    const float* nw  = (const float*)d_in[5];
    const int*   src = (const int*)d_in[6];
    const int*   rid = (const int*)d_in[7];
    float* out = (float*)d_out;

    int n    = in_sizes[0] / H;   // 150000
    int nrel = in_sizes[1] / H;   // 500

    size_t smB = (size_t)(H * H + 2 * H + B_WARPS * B_RPW * H) * sizeof(float);
    size_t smO = (size_t)(H * H + B_WARPS * B_RPW * H) * sizeof(float);
    cudaFuncSetAttribute(knode, cudaFuncAttributeMaxDynamicSharedMemorySize, (int)smB);
    cudaFuncSetAttribute(kout,  cudaFuncAttributeMaxDynamicSharedMemorySize, (int)smO);

    krel<<<nrel, H>>>(rel, W_r, a);
    knode<<<(n + B_WARPS * B_RPW - 1) / (B_WARPS * B_RPW), 256, smB>>>(ent, W, a, n);
    kgather<<<(n + G_WARPS - 1) / G_WARPS, 256>>>(src, rid, n);
    kout<<<(n + B_WARPS * B_RPW - 1) / (B_WARPS * B_RPW), 256, smO>>>(nw, out, n);
}

// round 8
// speedup vs baseline: 2.4166x; 2.3488x over previous
#include <cuda_runtime.h>
#include <cuda_bf16.h>
#include <math.h>
#include <stdint.h>

#define N_ENT_MAX 150016
#define H 128
#define DEG 32
#define TOPK 10
#define TILE_M 128
#define K_PAD 136     // bf16 elems per smem row (272B) -> conflict-free ldmatrix
#define D_PAD 132     // f32 elems per D smem row

// -------- device scratch (no allocs allowed) --------
__device__ float g_h_node[N_ENT_MAX * H];
__device__ float g_neigh[N_ENT_MAX * H];
__device__ float g_s_src[N_ENT_MAX];
__device__ float g_s_dst[N_ENT_MAX];
__device__ float g_h_rel[512 * H];
__device__ float g_s_rel[512];
// Pre-transposed B operands: B[n][k] = Wmat[k][n], bf16 hi/lo, rows padded to K_PAD
__device__ __align__(16) __nv_bfloat16 g_BW_hi[H * K_PAD];
__device__ __align__(16) __nv_bfloat16 g_BW_lo[H * K_PAD];
__device__ __align__(16) __nv_bfloat16 g_BN_hi[H * K_PAD];
__device__ __align__(16) __nv_bfloat16 g_BN_lo[H * K_PAD];

// ---------------- helpers ---------------------------
__device__ __forceinline__ uint32_t smem_u32(const void* p) {
    uint32_t a;
    asm("{ .reg .u64 t; cvta.to.shared.u64 t, %1; cvt.u32.u64 %0, t; }"
        : "=r"(a) : "l"(p));
    return a;
}

#define LDMX4(r0, r1, r2, r3, addr)                                             \
    asm volatile("ldmatrix.sync.aligned.m8n8.x4.shared.b16 {%0,%1,%2,%3}, [%4];"\
                 : "=r"(r0), "=r"(r1), "=r"(r2), "=r"(r3) : "r"(addr))

__device__ __forceinline__ void mma16816(float* c, uint32_t a0, uint32_t a1,
                                         uint32_t a2, uint32_t a3,
                                         uint32_t b0, uint32_t b1) {
    asm volatile(
        "mma.sync.aligned.m16n8k16.row.col.f32.bf16.bf16.f32 "
        "{%0,%1,%2,%3}, {%4,%5,%6,%7}, {%8,%9}, {%0,%1,%2,%3};"
        : "+f"(c[0]), "+f"(c[1]), "+f"(c[2]), "+f"(c[3])
        : "r"(a0), "r"(a1), "r"(a2), "r"(a3), "r"(b0), "r"(b1));
}

// ============ prep: B[n][k] = src[k][n] as bf16 hi/lo ======================
__global__ void kprepB(const float* __restrict__ W, const float* __restrict__ NW) {
    int tid = blockIdx.x * blockDim.x + threadIdx.x;
    if (tid >= H * H) return;
    int k = tid >> 7, nn = tid & 127;
    int off = nn * K_PAD + k;
    {
        float f = W[tid];
        __nv_bfloat16 hi = __float2bfloat16_rn(f);
        g_BW_hi[off] = hi;
        g_BW_lo[off] = __float2bfloat16_rn(f - __bfloat162float(hi));
    }
    {
        float f = NW[tid];
        __nv_bfloat16 hi = __float2bfloat16_rn(f);
        g_BN_hi[off] = hi;
        g_BN_lo[off] = __float2bfloat16_rn(f - __bfloat162float(hi));
    }
}

// ===================== kernel A: h_rel + s_rel (tiny) ======================
__global__ void krel(const float* __restrict__ rel_emb,
                     const float* __restrict__ W_r,
                     const float* __restrict__ a) {
    int r = blockIdx.x;
    int j = threadIdx.x;                 // 128 threads
    const float* x = rel_emb + r * H;
    float acc = 0.f;
#pragma unroll 8
    for (int h = 0; h < H; ++h) acc = fmaf(x[h], W_r[h * H + j], acc);
    g_h_rel[r * H + j] = acc;
    __shared__ float red[H];
    red[j] = acc * a[2 * H + j];
    __syncthreads();
    for (int off = 64; off > 0; off >>= 1) {
        if (j < off) red[j] += red[j + off];
        __syncthreads();
    }
    if (j == 0) g_s_rel[r] = red[0];
}

// ====== warp-MMA GEMM: Y[128 x 128 tile] = X @ Wmat (+ epilogue) ===========
// MODE 0: X=ent_emb, writes g_h_node + s_src/s_dst  (B = g_BW)
// MODE 1: X=g_neigh, writes out = tanh(.)           (B = g_BN)
// SMEM bytes: Ahi@0 (34816), Alo@34816, Bhi@69632, Blo@104448,
//             a1@139264, a2@139776; D(f32,128x132) reuses @0.
#define SM_AHI 0
#define SM_ALO 34816
#define SM_BHI 69632
#define SM_BLO 104448
#define SM_A1  139264
#define SM_A2  139776
#define SM_TOTAL 140288

template <int MODE>
__global__ void __launch_bounds__(256) kgemm(const float* __restrict__ Xin,
                                             const float* __restrict__ avec,
                                             float* __restrict__ out, int n) {
    extern __shared__ char sm[];
    uint32_t sb = smem_u32(sm);
    float* a1s = (float*)(sm + SM_A1);
    float* a2s = (float*)(sm + SM_A2);
    float* D = (float*)sm;               // reuses A region after MMA
    int tid = threadIdx.x;
    int w = tid >> 5, l = tid & 31;
    int wm = w >> 2, wn = w & 3;         // warp grid 2 (M) x 4 (N)
    int quad = l >> 3, lrow = l & 7;

    if (MODE == 0 && tid < 128) { a1s[tid] = avec[tid]; a2s[tid] = avec[H + tid]; }

    // ---- stage B (hi+lo, 2x34816B) ----
    {
        const uint4* bh = (const uint4*)(MODE == 0 ? (const void*)g_BW_hi : (const void*)g_BN_hi);
        const uint4* bl = (const uint4*)(MODE == 0 ? (const void*)g_BW_lo : (const void*)g_BN_lo);
        uint4* dh = (uint4*)(sm + SM_BHI);
        uint4* dl = (uint4*)(sm + SM_BLO);
        for (int i = tid; i < (H * K_PAD * 2) / 16; i += 256) { dh[i] = bh[i]; dl[i] = bl[i]; }
    }

    // ---- stage A: load fp32 rows, split bf16 hi/lo ----
    const float* X = (MODE == 0) ? Xin : g_neigh;
    int row0 = blockIdx.x * TILE_M;
    const float4* X4 = (const float4*)X;
    __nv_bfloat16* Ahi = (__nv_bfloat16*)(sm + SM_AHI);
    __nv_bfloat16* Alo = (__nv_bfloat16*)(sm + SM_ALO);
#pragma unroll
    for (int it = 0; it < 16; ++it) {
        int idx = it * 256 + tid;            // 4096 float4s
        int r = idx >> 5, s = idx & 31;
        int row = row0 + r;
        float4 v = make_float4(0.f, 0.f, 0.f, 0.f);
        if (row < n) v = X4[(size_t)row * 32 + s];
        __nv_bfloat16 h0 = __float2bfloat16_rn(v.x);
        __nv_bfloat16 h1 = __float2bfloat16_rn(v.y);
        __nv_bfloat16 h2 = __float2bfloat16_rn(v.z);
        __nv_bfloat16 h3 = __float2bfloat16_rn(v.w);
        __nv_bfloat162 ph0 = __halves2bfloat162(h0, h1);
        __nv_bfloat162 ph1 = __halves2bfloat162(h2, h3);
        uint2 uh; uh.x = *(uint32_t*)&ph0; uh.y = *(uint32_t*)&ph1;
        *(uint2*)(Ahi + r * K_PAD + 4 * s) = uh;
        __nv_bfloat162 pl0 = __halves2bfloat162(
            __float2bfloat16_rn(v.x - __bfloat162float(h0)),
            __float2bfloat16_rn(v.y - __bfloat162float(h1)));
        __nv_bfloat162 pl1 = __halves2bfloat162(
            __float2bfloat16_rn(v.z - __bfloat162float(h2)),
            __float2bfloat16_rn(v.w - __bfloat162float(h3)));
        uint2 ul; ul.x = *(uint32_t*)&pl0; ul.y = *(uint32_t*)&pl1;
        *(uint2*)(Alo + r * K_PAD + 4 * s) = ul;
    }
    __syncthreads();

    // ---- 3-pass warp MMA: AhBh + AhBl + AlBh ----
    float acc[4][4][4];                  // [m-tile][n8-tile][frag]
#pragma unroll
    for (int i = 0; i < 4; i++)
#pragma unroll
        for (int j = 0; j < 4; j++)
#pragma unroll
            for (int q = 0; q < 4; q++) acc[i][j][q] = 0.f;

    // per-lane ldmatrix byte offsets within a tile
    uint32_t a_loff = (uint32_t)(((lrow + (quad & 1) * 8) * K_PAD + (quad >> 1) * 8) * 2);
    uint32_t b_loff = (uint32_t)(((lrow + (quad >> 1) * 8) * K_PAD + (quad & 1) * 8) * 2);

#pragma unroll
    for (int pass = 0; pass < 3; pass++) {
        uint32_t abase = sb + (pass == 2 ? SM_ALO : SM_AHI);
        uint32_t bbase = sb + (pass == 1 ? SM_BLO : SM_BHI);
        uint32_t arow = abase + (uint32_t)(wm * 64) * (K_PAD * 2) + a_loff;
        uint32_t brow = bbase + (uint32_t)(wn * 32) * (K_PAD * 2) + b_loff;
#pragma unroll
        for (int ks = 0; ks < 8; ks++) {
            uint32_t k0 = ks * 32;       // 16 bf16 = 32 bytes
            uint32_t af[4][4], bf[2][4];
#pragma unroll
            for (int mt = 0; mt < 4; mt++)
                LDMX4(af[mt][0], af[mt][1], af[mt][2], af[mt][3],
                      arow + (uint32_t)(mt * 16) * (K_PAD * 2) + k0);
#pragma unroll
            for (int nt = 0; nt < 2; nt++)
                LDMX4(bf[nt][0], bf[nt][1], bf[nt][2], bf[nt][3],
                      brow + (uint32_t)(nt * 16) * (K_PAD * 2) + k0);
#pragma unroll
            for (int mt = 0; mt < 4; mt++)
#pragma unroll
                for (int q = 0; q < 4; q++)
                    mma16816(acc[mt][q], af[mt][0], af[mt][1], af[mt][2], af[mt][3],
                             bf[q >> 1][(q & 1) * 2], bf[q >> 1][(q & 1) * 2 + 1]);
        }
    }
    __syncthreads();                     // all ldmatrix reads done before D overwrite

    // ---- frags -> D smem (row pad 132) ----
#pragma unroll
    for (int mt = 0; mt < 4; mt++) {
        int row = wm * 64 + mt * 16 + (l >> 2);
#pragma unroll
        for (int q = 0; q < 4; q++) {
            int col = wn * 32 + q * 8 + 2 * (l & 3);
            *(float2*)(D + row * D_PAD + col) = make_float2(acc[mt][q][0], acc[mt][q][1]);
            *(float2*)(D + (row + 8) * D_PAD + col) = make_float2(acc[mt][q][2], acc[mt][q][3]);
        }
    }
    __syncthreads();

    // ---- epilogue ----
    if (MODE == 0) {
        // coalesced copy D -> g_h_node
#pragma unroll
        for (int it = 0; it < 16; ++it) {
            int idx = it * 256 + tid;
            int r = idx >> 5, s = idx & 31;
            int row = row0 + r;
            if (row < n) {
                float4 v = *(float4*)(D + r * D_PAD + 4 * s);
                *(float4*)(g_h_node + (size_t)row * H + 4 * s) = v;
            }
        }
        // per-row dots: threads 0-127 -> s_src, 128-255 -> s_dst
        int r = tid & 127;
        int row = row0 + r;
        if (row < n) {
            const float* av = (tid < 128) ? a1s : a2s;
            float p = 0.f;
            const float* dr = D + r * D_PAD;
#pragma unroll 8
            for (int c = 0; c < H; c++) p = fmaf(dr[c], av[c], p);
            if (tid < 128) g_s_src[row] = p; else g_s_dst[row] = p;
        }
    } else {
#pragma unroll
        for (int it = 0; it < 16; ++it) {
            int idx = it * 256 + tid;
            int r = idx >> 5, s = idx & 31;
            int row = row0 + r;
            if (row < n) {
                float4 v = *(float4*)(D + r * D_PAD + 4 * s);
                *(float4*)(out + (size_t)row * H + 4 * s) =
                    make_float4(tanhf(v.x), tanhf(v.y), tanhf(v.z), tanhf(v.w));
            }
        }
    }
}

// ====== kgather: score -> top10 -> softmax -> gather-agg -> g_neigh =======
#define G_WARPS 8
__global__ void __launch_bounds__(256) kgather(const int* __restrict__ src,
                                               const int* __restrict__ rid, int n) {
    __shared__ float ats[G_WARPS][16];
    __shared__ int   sks[G_WARPS][16];
    __shared__ int   rks[G_WARPS][16];
    int tid = threadIdx.x;
    int w = tid >> 5, l = tid & 31;
    int node = blockIdx.x * G_WARPS + w;
    if (node >= n) return;

    float sdst = g_s_dst[node];
    int s = src[node * DEG + l];
    int r = rid[node * DEG + l];
    float v = (g_s_src[s] + sdst) + g_s_rel[r];
    float sc = (v >= 0.f) ? v : 0.2f * v;

    int rank = 0;
#pragma unroll
    for (int j = 0; j < DEG; j++) {
        float vj = __shfl_sync(0xffffffffu, sc, j);
        rank += (vj > sc) || (vj == sc && j < l);
    }
    bool sel = (rank < TOPK);

    float m = sel ? sc : __int_as_float(0xff800000);
#pragma unroll
    for (int off = 16; off; off >>= 1) m = fmaxf(m, __shfl_xor_sync(0xffffffffu, m, off));
    float e = sel ? expf(sc - m) : 0.f;
    float z = e;
#pragma unroll
    for (int off = 16; off; off >>= 1) z += __shfl_xor_sync(0xffffffffu, z, off);
    float attn = e / z;

    if (sel) { ats[w][rank] = attn; sks[w][rank] = s; rks[w][rank] = r; }
    __syncwarp();

    float4 acc = make_float4(0.f, 0.f, 0.f, 0.f);
#pragma unroll
    for (int k = 0; k < TOPK; k++) {
        int sk = sks[w][k], rk = rks[w][k];
        float ak = ats[w][k];
        float4 hn = *(const float4*)(g_h_node + (size_t)sk * H + 4 * l);
        float4 hr = *(const float4*)(g_h_rel + rk * H + 4 * l);
        acc.x = fmaf(ak, hn.x + hr.x, acc.x);
        acc.y = fmaf(ak, hn.y + hr.y, acc.y);
        acc.z = fmaf(ak, hn.z + hr.z, acc.z);
        acc.w = fmaf(ak, hn.w + hr.w, acc.w);
    }
    *(float4*)(g_neigh + (size_t)node * H + 4 * l) = acc;
}

// ============================== launch =====================================
extern "C" void kernel_launch(void* const* d_in, const int* in_sizes, int n_in,
                              void* d_out, int out_size) {
    const float* ent = (const float*)d_in[0];
    const float* rel = (const float*)d_in[1];
    const float* W   = (const float*)d_in[2];
    const float* W_r = (const float*)d_in[3];
    const float* a   = (const float*)d_in[4];
    const float* nw  = (const float*)d_in[5];
    const int*   src = (const int*)d_in[6];
    const int*   rid = (const int*)d_in[7];
    float* out = (float*)d_out;

    int n    = in_sizes[0] / H;   // 150000
    int nrel = in_sizes[1] / H;   // 500
    int tiles = (n + TILE_M - 1) / TILE_M;

    cudaFuncSetAttribute(kgemm<0>, cudaFuncAttributeMaxDynamicSharedMemorySize, SM_TOTAL);
    cudaFuncSetAttribute(kgemm<1>, cudaFuncAttributeMaxDynamicSharedMemorySize, SM_TOTAL);

    kprepB<<<(H * H + 255) / 256, 256>>>(W, nw);
    krel<<<nrel, H>>>(rel, W_r, a);
    kgemm<0><<<tiles, 256, SM_TOTAL>>>(ent, a, nullptr, n);
    kgather<<<(n + G_WARPS - 1) / G_WARPS, 256>>>(src, rid, n);
    kgemm<1><<<tiles, 256, SM_TOTAL>>>(nullptr, a, out, n);
}